// round 11
// baseline (speedup 1.0000x reference)
#include <cuda_runtime.h>

// quadLayer: out[b,h,w, c*512 + a*32 + f] =
//   sum_m p[a][m] W1[c][m][f] + sum_{m1,m2} p[a][m1] p[a][m2] W2[c][m1*4+m2][f]
// p[a][mm] = x[b, 2h+((a>>2)>>1), 2w+((a>>2)&1), 4*(a&3)+mm].
//
// R11 = R9 (interleaved 2-plane Horner, 3 CTAs/SM, .cs stores) but with the
// smem feature stage DELETED: the a-pair {p[2ap], p[2ap+1]} is 8 consecutive
// channels of one x position = 2 adjacent float4s, loaded warp-uniform via
// LDG.128 (same-address broadcast dedups; x is L1-resident) and packed into
// f32x2 with mov.b64 on the idle ALU pipe. No smem, no __syncthreads.

#define NPIX 4
#define THREADS 256

__device__ __forceinline__ unsigned long long pack2(float lo, float hi) {
    unsigned long long r;
    asm("mov.b64 %0, {%1,%2};" : "=l"(r) : "f"(lo), "f"(hi));
    return r;
}

__device__ __forceinline__ void fma2(unsigned long long &d,
                                     unsigned long long a,
                                     unsigned long long b) {
    asm("fma.rn.f32x2 %0, %1, %2, %0;" : "+l"(d) : "l"(a), "l"(b));
}

__device__ __forceinline__ unsigned long long fma2n(unsigned long long a,
                                                    unsigned long long b,
                                                    unsigned long long c) {
    unsigned long long d;
    asm("fma.rn.f32x2 %0, %1, %2, %3;" : "=l"(d) : "l"(a), "l"(b), "l"(c));
    return d;
}

__device__ __forceinline__ unsigned long long mul2(unsigned long long a,
                                                   unsigned long long b) {
    unsigned long long d;
    asm("mul.rn.f32x2 %0, %1, %2;" : "=l"(d) : "l"(a), "l"(b));
    return d;
}

__device__ __forceinline__ unsigned long long add2(unsigned long long a,
                                                   unsigned long long b) {
    unsigned long long r;
    asm("add.rn.f32x2 %0, %1, %2;" : "=l"(r) : "l"(a), "l"(b));
    return r;
}

__device__ __forceinline__ void store2(float* p, unsigned long long s) {
    float lo, hi;
    asm("mov.b64 {%0,%1}, %2;" : "=f"(lo), "=f"(hi) : "l"(s));
    asm("st.global.cs.f32 [%0], %1;" :: "l"(p),      "f"(lo) : "memory");
    asm("st.global.cs.f32 [%0], %1;" :: "l"(p + 32), "f"(hi) : "memory");
}

__global__ void __launch_bounds__(THREADS, 3)
quad_kernel(const float* __restrict__ x,
            const float* __restrict__ W1,
            const float* __restrict__ W2,
            float* __restrict__ out)
{
    const int t  = threadIdx.x;
    const int c0 = t >> 5;   // 0..7  (planes c0 and c0+8)
    const int f  = t & 31;   // 0..31

    // ---- weights (duplicated f32x2), Horner layout ----
    unsigned long long linA[4], linB[4], qA[10], qB[10];
    {
        const float* w1a = W1 + c0 * 128 + f;
        const float* w1b = W1 + (c0 + 8) * 128 + f;
        const float* w2a = W2 + c0 * 512 + f;
        const float* w2b = W2 + (c0 + 8) * 512 + f;
#pragma unroll
        for (int m = 0; m < 4; m++) {
            float a = w1a[m * 32], b = w1b[m * 32];
            linA[m] = pack2(a, a);
            linB[m] = pack2(b, b);
        }
        int k = 0;
#pragma unroll
        for (int m1 = 0; m1 < 4; m1++)
#pragma unroll
            for (int m2 = m1; m2 < 4; m2++) {
                float a, b;
                if (m1 == m2) {
                    a = w2a[(5 * m1) * 32];
                    b = w2b[(5 * m1) * 32];
                } else {
                    a = w2a[(m1 * 4 + m2) * 32] + w2a[(m2 * 4 + m1) * 32];
                    b = w2b[(m1 * 4 + m2) * 32] + w2b[(m2 * 4 + m1) * 32];
                }
                qA[k] = pack2(a, a);
                qB[k] = pack2(b, b);
                k++;
            }
    }

    // output pointers for the two planes
    float* outA = out + (size_t)blockIdx.x * NPIX * 8192 + (size_t)(c0 * 512 + f);
    float* outB = outA + 8 * 512;

    // x float-offsets for ap = 0..7:  i(ap)=ap>>2, j(ap)=(ap>>1)&1, half=ap&1
    //   off = i*64*16 + j*16 + half*8
    const int XOFF[8] = {0, 8, 16, 24, 1024, 1032, 1040, 1048};

#pragma unroll 1
    for (int pix = 0; pix < NPIX; pix++) {
        // pixel base in x
        const int g  = blockIdx.x * NPIX + pix;
        const int b  = g >> 10;
        const int h  = (g >> 5) & 31;
        const int wc = g & 31;
        const float* xp = x + (size_t)(b * 65536 + h * 2048 + wc * 32);

#pragma unroll
        for (int ap = 0; ap < 8; ap++) {
            // warp-uniform loads: p[2ap][0..3] and p[2ap+1][0..3]
            const float4 v0 = __ldg((const float4*)(xp + XOFF[ap]));
            const float4 v1 = __ldg((const float4*)(xp + XOFF[ap] + 4));
            const unsigned long long pp0 = pack2(v0.x, v1.x);
            const unsigned long long pp1 = pack2(v0.y, v1.y);
            const unsigned long long pp2 = pack2(v0.z, v1.z);
            const unsigned long long pp3 = pack2(v0.w, v1.w);

            // interleaved Horner for planes A and B
            // q idx: (0,0)=0 (0,1)=1 (0,2)=2 (0,3)=3 (1,1)=4 (1,2)=5 (1,3)=6
            //        (2,2)=7 (2,3)=8 (3,3)=9
            unsigned long long tA0 = fma2n(pp0, qA[0], linA[0]);
            unsigned long long tB0 = fma2n(pp0, qB[0], linB[0]);
            unsigned long long tA1 = fma2n(pp1, qA[4], linA[1]);
            unsigned long long tB1 = fma2n(pp1, qB[4], linB[1]);
            unsigned long long tA2 = fma2n(pp2, qA[7], linA[2]);
            unsigned long long tB2 = fma2n(pp2, qB[7], linB[2]);
            unsigned long long tA3 = fma2n(pp3, qA[9], linA[3]);
            unsigned long long tB3 = fma2n(pp3, qB[9], linB[3]);
            fma2(tA0, pp1, qA[1]);  fma2(tB0, pp1, qB[1]);
            fma2(tA1, pp2, qA[5]);  fma2(tB1, pp2, qB[5]);
            fma2(tA2, pp3, qA[8]);  fma2(tB2, pp3, qB[8]);
            fma2(tA0, pp2, qA[2]);  fma2(tB0, pp2, qB[2]);
            fma2(tA1, pp3, qA[6]);  fma2(tB1, pp3, qB[6]);
            fma2(tA0, pp3, qA[3]);  fma2(tB0, pp3, qB[3]);

            unsigned long long sA0 = mul2(pp0, tA0);
            unsigned long long sB0 = mul2(pp0, tB0);
            unsigned long long sA1 = mul2(pp1, tA1);
            unsigned long long sB1 = mul2(pp1, tB1);
            fma2(sA0, pp2, tA2);  fma2(sB0, pp2, tB2);
            fma2(sA1, pp3, tA3);  fma2(sB1, pp3, tB3);

            store2(outA + (2 * ap) * 32, add2(sA0, sA1));
            store2(outB + (2 * ap) * 32, add2(sB0, sB1));
        }
        outA += 8192;
        outB += 8192;
    }
}

extern "C" void kernel_launch(void* const* d_in, const int* in_sizes, int n_in,
                              void* d_out, int out_size) {
    const float* x  = (const float*)d_in[0];
    const float* W1 = (const float*)d_in[1];
    const float* W2 = (const float*)d_in[2];
    float* out = (float*)d_out;
    quad_kernel<<<8192 / NPIX, THREADS>>>(x, W1, W2, out);
}

// round 12
// speedup vs baseline: 1.6040x; 1.6040x over previous
#include <cuda_runtime.h>

// quadLayer: out[b,h,w, c*512 + a*32 + f] =
//   sum_m p[a][m] W1[c][m][f] + sum_{m1,m2} p[a][m1] p[a][m2] W2[c][m1*4+m2][f]
// p[a][mm] = x[b, 2h+((a>>2)>>1), 2w+((a>>2)&1), 4*(a&3)+mm]  (one float4 of x).
//
// R12 = R9 (interleaved 2-plane Horner via a-parity-packed smem, 3 CTAs/SM,
// .cs stores) with NPIX 4 -> 2: grid 4096 halves per-SM CTA-count imbalance
// and the partial-wave tail. Smem layout is load-bearing: operands arrive
// pre-paired for f32x2, zero packing ALU (R11 showed the LDG+mov path loses).

#define NPIX 2
#define THREADS 256

__device__ __forceinline__ unsigned long long pack2(float lo, float hi) {
    unsigned long long r;
    asm("mov.b64 %0, {%1,%2};" : "=l"(r) : "f"(lo), "f"(hi));
    return r;
}

__device__ __forceinline__ void fma2(unsigned long long &d,
                                     unsigned long long a,
                                     unsigned long long b) {
    asm("fma.rn.f32x2 %0, %1, %2, %0;" : "+l"(d) : "l"(a), "l"(b));
}

__device__ __forceinline__ unsigned long long fma2n(unsigned long long a,
                                                    unsigned long long b,
                                                    unsigned long long c) {
    unsigned long long d;
    asm("fma.rn.f32x2 %0, %1, %2, %3;" : "=l"(d) : "l"(a), "l"(b), "l"(c));
    return d;
}

__device__ __forceinline__ unsigned long long mul2(unsigned long long a,
                                                   unsigned long long b) {
    unsigned long long d;
    asm("mul.rn.f32x2 %0, %1, %2;" : "=l"(d) : "l"(a), "l"(b));
    return d;
}

__device__ __forceinline__ unsigned long long add2(unsigned long long a,
                                                   unsigned long long b) {
    unsigned long long r;
    asm("add.rn.f32x2 %0, %1, %2;" : "=l"(r) : "l"(a), "l"(b));
    return r;
}

__device__ __forceinline__ void store2(float* p, unsigned long long s) {
    float lo, hi;
    asm("mov.b64 {%0,%1}, %2;" : "=f"(lo), "=f"(hi) : "l"(s));
    asm("st.global.cs.f32 [%0], %1;" :: "l"(p),      "f"(lo) : "memory");
    asm("st.global.cs.f32 [%0], %1;" :: "l"(p + 32), "f"(hi) : "memory");
}

__global__ void __launch_bounds__(THREADS, 3)
quad_kernel(const float* __restrict__ x,
            const float* __restrict__ W1,
            const float* __restrict__ W2,
            float* __restrict__ out)
{
    // base values only: NPIX * 8 ap * 4 m * 2 parity floats = 512 B
    __shared__ __align__(16) float pbase[NPIX * 8 * 4 * 2];

    const int t  = threadIdx.x;
    const int c0 = t >> 5;   // 0..7  (planes c0 and c0+8)
    const int f  = t & 31;   // 0..31

    // ---- weights (duplicated f32x2), Horner layout ----
    unsigned long long linA[4], linB[4], qA[10], qB[10];
    {
        const float* w1a = W1 + c0 * 128 + f;
        const float* w1b = W1 + (c0 + 8) * 128 + f;
        const float* w2a = W2 + c0 * 512 + f;
        const float* w2b = W2 + (c0 + 8) * 512 + f;
#pragma unroll
        for (int m = 0; m < 4; m++) {
            float a = w1a[m * 32], b = w1b[m * 32];
            linA[m] = pack2(a, a);
            linB[m] = pack2(b, b);
        }
        int k = 0;
#pragma unroll
        for (int m1 = 0; m1 < 4; m1++)
#pragma unroll
            for (int m2 = m1; m2 < 4; m2++) {
                float a, b;
                if (m1 == m2) {
                    a = w2a[(5 * m1) * 32];
                    b = w2b[(5 * m1) * 32];
                } else {
                    a = w2a[(m1 * 4 + m2) * 32] + w2a[(m2 * 4 + m1) * 32];
                    b = w2b[(m1 * 4 + m2) * 32] + w2b[(m2 * 4 + m1) * 32];
                }
                qA[k] = pack2(a, a);
                qB[k] = pack2(b, b);
                k++;
            }
    }

    // ---- base-value build: one thread per (pix, a); NPIX*16 = 32 threads ----
    if (t < NPIX * 16) {
        const int pix = t >> 4;
        const int a   = t & 15;
        const int g   = blockIdx.x * NPIX + pix;   // global pixel id
        const int b   = g >> 10;
        const int h   = (g >> 5) & 31;
        const int wc  = g & 31;
        const int m   = a >> 2;
        const int i   = m >> 1;
        const int j   = m & 1;
        const int ch0 = (a & 3) * 4;
        const float4 v = *reinterpret_cast<const float4*>(
            x + (((b * 64 + 2 * h + i) * 64) + (2 * wc + j)) * 16 + ch0);
        float* fb = &pbase[(pix * 8 + (a >> 1)) * 8 + (a & 1)];
        fb[0] = v.x; fb[2] = v.y; fb[4] = v.z; fb[6] = v.w;
    }
    __syncthreads();

    // incremental output pointers for the two planes
    float* outA = out + (size_t)blockIdx.x * NPIX * 8192 + (size_t)(c0 * 512 + f);
    float* outB = outA + 8 * 512;
    unsigned int saddr = (unsigned int)__cvta_generic_to_shared(pbase);

#pragma unroll 1
    for (int pix = 0; pix < NPIX; pix++) {
#pragma unroll
        for (int ap = 0; ap < 8; ap++) {
            unsigned long long pp0, pp1, pp2, pp3;
            asm("ld.shared.v2.u64 {%0,%1}, [%2];"
                : "=l"(pp0), "=l"(pp1) : "r"(saddr));
            asm("ld.shared.v2.u64 {%0,%1}, [%2];"
                : "=l"(pp2), "=l"(pp3) : "r"(saddr + 16));
            saddr += 32;

            // interleaved Horner for planes A and B
            // q idx: (0,0)=0 (0,1)=1 (0,2)=2 (0,3)=3 (1,1)=4 (1,2)=5 (1,3)=6
            //        (2,2)=7 (2,3)=8 (3,3)=9
            unsigned long long tA0 = fma2n(pp0, qA[0], linA[0]);
            unsigned long long tB0 = fma2n(pp0, qB[0], linB[0]);
            unsigned long long tA1 = fma2n(pp1, qA[4], linA[1]);
            unsigned long long tB1 = fma2n(pp1, qB[4], linB[1]);
            unsigned long long tA2 = fma2n(pp2, qA[7], linA[2]);
            unsigned long long tB2 = fma2n(pp2, qB[7], linB[2]);
            unsigned long long tA3 = fma2n(pp3, qA[9], linA[3]);
            unsigned long long tB3 = fma2n(pp3, qB[9], linB[3]);
            fma2(tA0, pp1, qA[1]);  fma2(tB0, pp1, qB[1]);
            fma2(tA1, pp2, qA[5]);  fma2(tB1, pp2, qB[5]);
            fma2(tA2, pp3, qA[8]);  fma2(tB2, pp3, qB[8]);
            fma2(tA0, pp2, qA[2]);  fma2(tB0, pp2, qB[2]);
            fma2(tA1, pp3, qA[6]);  fma2(tB1, pp3, qB[6]);
            fma2(tA0, pp3, qA[3]);  fma2(tB0, pp3, qB[3]);

            unsigned long long sA0 = mul2(pp0, tA0);
            unsigned long long sB0 = mul2(pp0, tB0);
            unsigned long long sA1 = mul2(pp1, tA1);
            unsigned long long sB1 = mul2(pp1, tB1);
            fma2(sA0, pp2, tA2);  fma2(sB0, pp2, tB2);
            fma2(sA1, pp3, tA3);  fma2(sB1, pp3, tB3);

            store2(outA + (2 * ap) * 32, add2(sA0, sA1));
            store2(outB + (2 * ap) * 32, add2(sB0, sB1));
        }
        outA += 8192;
        outB += 8192;
    }
}

extern "C" void kernel_launch(void* const* d_in, const int* in_sizes, int n_in,
                              void* d_out, int out_size) {
    const float* x  = (const float*)d_in[0];
    const float* W1 = (const float*)d_in[1];
    const float* W2 = (const float*)d_in[2];
    float* out = (float*)d_out;
    quad_kernel<<<8192 / NPIX, THREADS>>>(x, W1, W2, out);
}

// round 13
// speedup vs baseline: 1.6278x; 1.0149x over previous
#include <cuda_runtime.h>

// quadLayer: out[b,h,w, c*512 + a*32 + f] =
//   sum_m p[a][m] W1[c][m][f] + sum_{m1,m2} p[a][m1] p[a][m2] W2[c][m1*4+m2][f]
// p[a][mm] = x[b, 2h+((a>>2)>>1), 2w+((a>>2)&1), 4*(a&3)+mm]  (one float4 of x).
//
// R13 = R9 structure (Horner symmetric quadratic, a-parity-packed smem,
// NPIX=4, 3 CTAs/SM, .cs stores) with a 1-deep software pipeline on the
// shared loads: iteration i+1's two LDS.128 issue before iteration i's
// compute, hiding the 29-cyc LDS latency behind 30 FFMA2. Planes A and B
// are serialized to keep peak regs <= 85 (3 CTAs resident).

#define NPIX 4
#define THREADS 256

__device__ __forceinline__ unsigned long long pack2(float lo, float hi) {
    unsigned long long r;
    asm("mov.b64 %0, {%1,%2};" : "=l"(r) : "f"(lo), "f"(hi));
    return r;
}

__device__ __forceinline__ void fma2(unsigned long long &d,
                                     unsigned long long a,
                                     unsigned long long b) {
    asm("fma.rn.f32x2 %0, %1, %2, %0;" : "+l"(d) : "l"(a), "l"(b));
}

__device__ __forceinline__ unsigned long long fma2n(unsigned long long a,
                                                    unsigned long long b,
                                                    unsigned long long c) {
    unsigned long long d;
    asm("fma.rn.f32x2 %0, %1, %2, %3;" : "=l"(d) : "l"(a), "l"(b), "l"(c));
    return d;
}

__device__ __forceinline__ unsigned long long mul2(unsigned long long a,
                                                   unsigned long long b) {
    unsigned long long d;
    asm("mul.rn.f32x2 %0, %1, %2;" : "=l"(d) : "l"(a), "l"(b));
    return d;
}

__device__ __forceinline__ unsigned long long add2(unsigned long long a,
                                                   unsigned long long b) {
    unsigned long long r;
    asm("add.rn.f32x2 %0, %1, %2;" : "=l"(r) : "l"(a), "l"(b));
    return r;
}

__device__ __forceinline__ void store2(float* p, unsigned long long s) {
    float lo, hi;
    asm("mov.b64 {%0,%1}, %2;" : "=f"(lo), "=f"(hi) : "l"(s));
    asm("st.global.cs.f32 [%0], %1;" :: "l"(p),      "f"(lo) : "memory");
    asm("st.global.cs.f32 [%0], %1;" :: "l"(p + 32), "f"(hi) : "memory");
}

// one plane of the Horner lattice; tight register lifetime
__device__ __forceinline__ unsigned long long plane_eval(
    unsigned long long pp0, unsigned long long pp1,
    unsigned long long pp2, unsigned long long pp3,
    const unsigned long long* __restrict__ lin,
    const unsigned long long* __restrict__ q)
{
    // q idx: (0,0)=0 (0,1)=1 (0,2)=2 (0,3)=3 (1,1)=4 (1,2)=5 (1,3)=6
    //        (2,2)=7 (2,3)=8 (3,3)=9
    unsigned long long t0 = fma2n(pp0, q[0], lin[0]);
    unsigned long long t1 = fma2n(pp1, q[4], lin[1]);
    unsigned long long t2 = fma2n(pp2, q[7], lin[2]);
    unsigned long long t3 = fma2n(pp3, q[9], lin[3]);
    fma2(t0, pp1, q[1]);
    fma2(t1, pp2, q[5]);
    fma2(t2, pp3, q[8]);
    fma2(t0, pp2, q[2]);
    fma2(t1, pp3, q[6]);
    fma2(t0, pp3, q[3]);
    unsigned long long s0 = mul2(pp0, t0);
    unsigned long long s1 = mul2(pp1, t1);
    fma2(s0, pp2, t2);
    fma2(s1, pp3, t3);
    return add2(s0, s1);
}

__global__ void __launch_bounds__(THREADS, 3)
quad_kernel(const float* __restrict__ x,
            const float* __restrict__ W1,
            const float* __restrict__ W2,
            float* __restrict__ out)
{
    // base values (NPIX*8 ap * 4 m * 2 parity floats = 1 KB) + 32B pad for
    // the final over-prefetch.
    __shared__ __align__(16) float pbase[NPIX * 8 * 4 * 2 + 8];

    const int t  = threadIdx.x;
    const int c0 = t >> 5;   // 0..7  (planes c0 and c0+8)
    const int f  = t & 31;   // 0..31

    // ---- weights (duplicated f32x2), Horner layout ----
    unsigned long long linA[4], linB[4], qA[10], qB[10];
    {
        const float* w1a = W1 + c0 * 128 + f;
        const float* w1b = W1 + (c0 + 8) * 128 + f;
        const float* w2a = W2 + c0 * 512 + f;
        const float* w2b = W2 + (c0 + 8) * 512 + f;
#pragma unroll
        for (int m = 0; m < 4; m++) {
            float a = w1a[m * 32], b = w1b[m * 32];
            linA[m] = pack2(a, a);
            linB[m] = pack2(b, b);
        }
        int k = 0;
#pragma unroll
        for (int m1 = 0; m1 < 4; m1++)
#pragma unroll
            for (int m2 = m1; m2 < 4; m2++) {
                float a, b;
                if (m1 == m2) {
                    a = w2a[(5 * m1) * 32];
                    b = w2b[(5 * m1) * 32];
                } else {
                    a = w2a[(m1 * 4 + m2) * 32] + w2a[(m2 * 4 + m1) * 32];
                    b = w2b[(m1 * 4 + m2) * 32] + w2b[(m2 * 4 + m1) * 32];
                }
                qA[k] = pack2(a, a);
                qB[k] = pack2(b, b);
                k++;
            }
    }

    // ---- base-value build: one thread per (pix, a); NPIX*16 = 64 threads ----
    if (t < NPIX * 16) {
        const int pix = t >> 4;
        const int a   = t & 15;
        const int g   = blockIdx.x * NPIX + pix;   // global pixel id
        const int b   = g >> 10;
        const int h   = (g >> 5) & 31;
        const int wc  = g & 31;
        const int m   = a >> 2;
        const int i   = m >> 1;
        const int j   = m & 1;
        const int ch0 = (a & 3) * 4;
        const float4 v = *reinterpret_cast<const float4*>(
            x + (((b * 64 + 2 * h + i) * 64) + (2 * wc + j)) * 16 + ch0);
        float* fb = &pbase[(pix * 8 + (a >> 1)) * 8 + (a & 1)];
        fb[0] = v.x; fb[2] = v.y; fb[4] = v.z; fb[6] = v.w;
    }
    __syncthreads();

    // incremental output pointers for the two planes
    float* outA = out + (size_t)blockIdx.x * NPIX * 8192 + (size_t)(c0 * 512 + f);
    float* outB = outA + 8 * 512;
    unsigned int saddr = (unsigned int)__cvta_generic_to_shared(pbase);

    // ---- software-pipelined main loop: prefetch depth 1 ----
    unsigned long long p0, p1, p2, p3;   // current operands
    asm("ld.shared.v2.u64 {%0,%1}, [%2];" : "=l"(p0), "=l"(p1) : "r"(saddr));
    asm("ld.shared.v2.u64 {%0,%1}, [%2];" : "=l"(p2), "=l"(p3) : "r"(saddr + 16));
    saddr += 32;

#pragma unroll 1
    for (int pix = 0; pix < NPIX; pix++) {
#pragma unroll
        for (int ap = 0; ap < 8; ap++) {
            // prefetch next iteration's operands (pad covers the last one)
            unsigned long long n0, n1, n2, n3;
            asm("ld.shared.v2.u64 {%0,%1}, [%2];"
                : "=l"(n0), "=l"(n1) : "r"(saddr));
            asm("ld.shared.v2.u64 {%0,%1}, [%2];"
                : "=l"(n2), "=l"(n3) : "r"(saddr + 16));
            saddr += 32;

            // plane A, then plane B (serialized to bound live registers)
            store2(outA + (2 * ap) * 32, plane_eval(p0, p1, p2, p3, linA, qA));
            store2(outB + (2 * ap) * 32, plane_eval(p0, p1, p2, p3, linB, qB));

            p0 = n0; p1 = n1; p2 = n2; p3 = n3;   // rotated away by unroll
        }
        outA += 8192;
        outB += 8192;
    }
}

extern "C" void kernel_launch(void* const* d_in, const int* in_sizes, int n_in,
                              void* d_out, int out_size) {
    const float* x  = (const float*)d_in[0];
    const float* W1 = (const float*)d_in[1];
    const float* W2 = (const float*)d_in[2];
    float* out = (float*)d_out;
    quad_kernel<<<8192 / NPIX, THREADS>>>(x, W1, W2, out);
}